// round 6
// baseline (speedup 1.0000x reference)
#include <cuda_runtime.h>
#include <cstdint>
#include <math.h>

#define BB   64
#define NN   64
#define DD   256
#define LAPD 16
#define MM   2016          // N*(N-1)/2
#define SEQ  2081          // 1 + N + M

// Scratch (no allocation allowed in kernel_launch)
__device__ float g_proju[BB * NN * DD];   // 4 MB (C folded in)
__device__ float g_projv[BB * NN * DD];   // 4 MB
__device__ unsigned short g_edge[BB * MM];
__device__ int g_count[BB];

// Map linear upper-tri index m -> (i, j), i<j, row-major (triu_indices order)
__device__ __forceinline__ void m2ij(int m, int& i, int& j) {
    int ii = (int)((127.0 - sqrt(16129.0 - 8.0 * (double)m)) * 0.5);
    if (ii < 0) ii = 0;
    if (ii > 62) ii = 62;
    while (ii < 62 && (ii + 1) * (127 - (ii + 1)) / 2 <= m) ii++;
    while (ii > 0 && ii * (127 - ii) / 2 > m) ii--;
    i = ii;
    j = ii + 1 + (m - ii * (127 - ii) / 2);
}

// Fused: blocks [0,256) = proj; blocks [256,320) = scan + edge mask tail.
__global__ void fused_proj_scan(const float* __restrict__ node_feats,
                                const float* __restrict__ eigvec,
                                const float* __restrict__ W_lap,
                                const float* __restrict__ W_edge,
                                const float* __restrict__ b_edge,
                                const float* __restrict__ type_embed,
                                const float* __restrict__ graph_tok,
                                const int*  __restrict__ adj,
                                float* __restrict__ out) {
    __shared__ float sh[256];
    int tid = threadIdx.x;

    if (blockIdx.x < 256) {
        // ---------------- proj ----------------
        int b  = blockIdx.x >> 2;
        int g  = blockIdx.x & 3;
        int n0 = g * 16;
        int d  = tid;

        float wl[LAPD], wu[LAPD], wv[LAPD];
#pragma unroll
        for (int l = 0; l < LAPD; l++) {
            wl[l] = __ldg(&W_lap[l * DD + d]);
            wu[l] = __ldg(&W_edge[(1 + l) * DD + d]);
            wv[l] = __ldg(&W_edge[(1 + LAPD + l) * DD + d]);
        }
        float Cd = __ldg(&W_edge[d]) + __ldg(&b_edge[d]) + __ldg(&type_embed[DD + d]);

        sh[tid] = eigvec[(size_t)(b * NN + n0) * LAPD + tid];
        __syncthreads();

#pragma unroll 4
        for (int n = 0; n < 16; n++) {
            int node = b * NN + n0 + n;
            float nt = node_feats[(size_t)node * DD + d];
            float pu = 0.f, pv = 0.f;
#pragma unroll
            for (int l = 0; l < LAPD; l++) {
                float ev = sh[n * LAPD + l];
                nt += ev * wl[l];
                pu += ev * wu[l];
                pv += ev * wv[l];
            }
            __stcs(&out[((size_t)b * SEQ + 1 + n0 + n) * DD + d], nt);
            g_proju[(size_t)node * DD + d] = pu + Cd;
            g_projv[(size_t)node * DD + d] = pv;
        }

        if (g == 0) {
            __stcs(&out[(size_t)b * SEQ * DD + d], graph_tok[d]);
            float* maskf = out + (size_t)BB * SEQ * DD;
            if (d < 1 + NN) maskf[(size_t)b * SEQ + d] = 0.f;
        }
    } else {
        // ---------------- scan + mask tail ----------------
        int b = blockIdx.x - 256;
        int* s = (int*)sh;
        const int* adjb = adj + (size_t)b * NN * NN;

        int m0 = tid * 8;
        int i, j;
        int v[8], ij[8];
        int local = 0;
        if (m0 < MM) {
            m2ij(m0, i, j);
#pragma unroll
            for (int q = 0; q < 8; q++) {
                int m = m0 + q;
                int val = 0, pack = 0;
                if (m < MM) {
                    pack = (i << 6) | j;
                    val = adjb[i * NN + j] > 0;
                    j++;
                    if (j == NN) { i++; j = i + 1; }
                }
                v[q] = val; ij[q] = pack;
                local += val;
            }
        } else {
#pragma unroll
            for (int q = 0; q < 8; q++) { v[q] = 0; ij[q] = 0; }
        }

        s[tid] = local;
        __syncthreads();
#pragma unroll
        for (int off = 1; off < 256; off <<= 1) {
            int add = (tid >= off) ? s[tid - off] : 0;
            __syncthreads();
            s[tid] += add;
            __syncthreads();
        }
        int pos = s[tid] - local;
#pragma unroll
        for (int q = 0; q < 8; q++) {
            if (v[q]) g_edge[b * MM + pos++] = (unsigned short)ij[q];
        }
        int total = s[255];
        if (tid == 255) g_count[b] = total;

        float* maskf = out + (size_t)BB * SEQ * DD + (size_t)b * SEQ + 1 + NN;
        for (int k = tid; k < MM; k += 256)
            maskf[k] = (k < total) ? 0.f : 1.f;
    }
}

// Edge kernel: grid (126, 64), 512 threads. 16 rows/block, 2 rows per 64-lane
// group. Gathers via LDG.128 (L2-resident scratch), results staged in a 16KB
// smem tile, then ONE cp.async.bulk (TMA) store per block -> bypasses STG LSU cost.
__global__ void __launch_bounds__(512, 4) edge_kernel(float* __restrict__ out) {
    __shared__ __align__(16) float tile[16 * DD];   // 16KB

    int b    = blockIdx.y;
    int r0   = blockIdx.x << 4;            // 16 rows per block
    int tid  = threadIdx.x;
    int rg   = tid >> 6;                   // 0..7
    int lane = tid & 63;

    int K = g_count[b];
    int k0 = r0 + 2 * rg;
    int k1 = k0 + 1;

    int p0 = (k0 < K) ? (int)g_edge[b * MM + k0] : -1;
    int p1 = (k1 < K) ? (int)g_edge[b * MM + k1] : -1;
    int s0 = p0 < 0 ? 0 : p0;
    int s1 = p1 < 0 ? 0 : p1;

    const float4* pu = (const float4*)(g_proju + (size_t)b * NN * DD);
    const float4* pv = (const float4*)(g_projv + (size_t)b * NN * DD);

    float4 a0 = __ldg(&pu[((s0 >> 6) << 6) + lane]);
    float4 c0 = __ldg(&pv[((s0 & 63) << 6) + lane]);
    float4 a1 = __ldg(&pu[((s1 >> 6) << 6) + lane]);
    float4 c1 = __ldg(&pv[((s1 & 63) << 6) + lane]);

    float4 v0 = make_float4(0.f, 0.f, 0.f, 0.f);
    float4 v1 = v0;
    if (p0 >= 0) v0 = make_float4(a0.x + c0.x, a0.y + c0.y, a0.z + c0.z, a0.w + c0.w);
    if (p1 >= 0) v1 = make_float4(a1.x + c1.x, a1.y + c1.y, a1.z + c1.z, a1.w + c1.w);

    float4* trow = (float4*)tile;
    trow[((2 * rg) << 6) + lane]     = v0;
    trow[((2 * rg + 1) << 6) + lane] = v1;

    __syncthreads();

    if (tid == 0) {
        // generic-proxy smem writes -> async-proxy bulk copy ordering
        asm volatile("fence.proxy.async.shared::cta;" ::: "memory");
        float* dst = out + ((size_t)b * SEQ + 1 + NN + r0) * DD;
        unsigned int saddr;
        asm("{ .reg .u64 t; cvta.to.shared.u64 t, %1; cvt.u32.u64 %0, t; }"
            : "=r"(saddr) : "l"(tile));
        asm volatile("cp.async.bulk.global.shared::cta.bulk_group [%0], [%1], %2;"
                     :: "l"(dst), "r"(saddr), "r"(16 * DD * 4) : "memory");
        asm volatile("cp.async.bulk.commit_group;" ::: "memory");
        asm volatile("cp.async.bulk.wait_group 0;" ::: "memory");
    }
}

extern "C" void kernel_launch(void* const* d_in, const int* in_sizes, int n_in,
                              void* d_out, int out_size) {
    const int*   adj        = (const int*)d_in[0];
    const float* node_feats = (const float*)d_in[1];
    const float* eigvec     = (const float*)d_in[2];
    const float* W_lap      = (const float*)d_in[3];
    const float* W_edge     = (const float*)d_in[4];
    const float* b_edge     = (const float*)d_in[5];
    const float* type_embed = (const float*)d_in[6];
    const float* graph_tok  = (const float*)d_in[7];
    float* out = (float*)d_out;

    fused_proj_scan<<<320, 256>>>(node_feats, eigvec, W_lap, W_edge, b_edge,
                                  type_embed, graph_tok, adj, out);
    edge_kernel<<<dim3(126, 64), 512>>>(out);
}

// round 8
// speedup vs baseline: 1.3364x; 1.3364x over previous
#include <cuda_runtime.h>
#include <cstdint>
#include <math.h>

#define BB   64
#define NN   64
#define DD   256
#define LAPD 16
#define MM   2016          // N*(N-1)/2
#define SEQ  2081          // 1 + N + M

// Scratch (no allocation allowed in kernel_launch)
__device__ float g_proju[BB * NN * DD];   // 4 MB (C folded in)
__device__ float g_projv[BB * NN * DD];   // 4 MB
__device__ unsigned short g_edge[BB * MM];
__device__ int g_count[BB];

// Map linear upper-tri index m -> (i, j), i<j, row-major (triu_indices order)
__device__ __forceinline__ void m2ij(int m, int& i, int& j) {
    int ii = (int)((127.0 - sqrt(16129.0 - 8.0 * (double)m)) * 0.5);
    if (ii < 0) ii = 0;
    if (ii > 62) ii = 62;
    while (ii < 62 && (ii + 1) * (127 - (ii + 1)) / 2 <= m) ii++;
    while (ii > 0 && ii * (127 - ii) / 2 > m) ii--;
    i = ii;
    j = ii + 1 + (m - ii * (127 - ii) / 2);
}

// Fused: blocks [0,256) = proj; blocks [256,320) = scan + edge mask tail.
__global__ void fused_proj_scan(const float* __restrict__ node_feats,
                                const float* __restrict__ eigvec,
                                const float* __restrict__ W_lap,
                                const float* __restrict__ W_edge,
                                const float* __restrict__ b_edge,
                                const float* __restrict__ type_embed,
                                const float* __restrict__ graph_tok,
                                const int*  __restrict__ adj,
                                float* __restrict__ out) {
    __shared__ float sh[256];
    int tid = threadIdx.x;

    if (blockIdx.x < 256) {
        // ---------------- proj ----------------
        int b  = blockIdx.x >> 2;
        int g  = blockIdx.x & 3;
        int n0 = g * 16;
        int d  = tid;

        float wl[LAPD], wu[LAPD], wv[LAPD];
#pragma unroll
        for (int l = 0; l < LAPD; l++) {
            wl[l] = __ldg(&W_lap[l * DD + d]);
            wu[l] = __ldg(&W_edge[(1 + l) * DD + d]);
            wv[l] = __ldg(&W_edge[(1 + LAPD + l) * DD + d]);
        }
        float Cd = __ldg(&W_edge[d]) + __ldg(&b_edge[d]) + __ldg(&type_embed[DD + d]);

        sh[tid] = eigvec[(size_t)(b * NN + n0) * LAPD + tid];
        __syncthreads();

#pragma unroll 4
        for (int n = 0; n < 16; n++) {
            int node = b * NN + n0 + n;
            float nt = node_feats[(size_t)node * DD + d];
            float pu = 0.f, pv = 0.f;
#pragma unroll
            for (int l = 0; l < LAPD; l++) {
                float ev = sh[n * LAPD + l];
                nt += ev * wl[l];
                pu += ev * wu[l];
                pv += ev * wv[l];
            }
            __stcs(&out[((size_t)b * SEQ + 1 + n0 + n) * DD + d], nt);
            g_proju[(size_t)node * DD + d] = pu + Cd;
            g_projv[(size_t)node * DD + d] = pv;
        }

        if (g == 0) {
            __stcs(&out[(size_t)b * SEQ * DD + d], graph_tok[d]);
            float* maskf = out + (size_t)BB * SEQ * DD;
            if (d < 1 + NN) maskf[(size_t)b * SEQ + d] = 0.f;
        }
    } else {
        // ---------------- scan + mask tail ----------------
        int b = blockIdx.x - 256;
        int* s = (int*)sh;
        const int* adjb = adj + (size_t)b * NN * NN;

        int m0 = tid * 8;
        int i, j;
        int v[8], ij[8];
        int local = 0;
        if (m0 < MM) {
            m2ij(m0, i, j);
#pragma unroll
            for (int q = 0; q < 8; q++) {
                int m = m0 + q;
                int val = 0, pack = 0;
                if (m < MM) {
                    pack = (i << 6) | j;
                    val = adjb[i * NN + j] > 0;
                    j++;
                    if (j == NN) { i++; j = i + 1; }
                }
                v[q] = val; ij[q] = pack;
                local += val;
            }
        } else {
#pragma unroll
            for (int q = 0; q < 8; q++) { v[q] = 0; ij[q] = 0; }
        }

        s[tid] = local;
        __syncthreads();
#pragma unroll
        for (int off = 1; off < 256; off <<= 1) {
            int add = (tid >= off) ? s[tid - off] : 0;
            __syncthreads();
            s[tid] += add;
            __syncthreads();
        }
        int pos = s[tid] - local;
#pragma unroll
        for (int q = 0; q < 8; q++) {
            if (v[q]) g_edge[b * MM + pos++] = (unsigned short)ij[q];
        }
        int total = s[255];
        if (tid == 255) g_count[b] = total;

        float* maskf = out + (size_t)BB * SEQ * DD + (size_t)b * SEQ + 1 + NN;
        for (int k = tid; k < MM; k += 256)
            maskf[k] = (k < total) ? 0.f : 1.f;
    }
}

// Edge kernel: grid (252, 64), 256 threads. 8 rows/block; each 64-lane group
// handles 2 ADJACENT rows (one u32 load covers both u16 edge indices).
// No smem, no division, branchless zeroing, streaming float4 stores.
__global__ void __launch_bounds__(256, 8) edge_kernel(float* __restrict__ out) {
    int b    = blockIdx.y;
    int tid  = threadIdx.x;
    int rg   = tid >> 6;                   // 0..3
    int lane = tid & 63;
    int k0   = (blockIdx.x << 3) + (rg << 1);   // adjacent pair k0, k0+1
    int K    = g_count[b];

    // one 32-bit load -> both u16 indices (aligned: k0 even)
    unsigned int pack2 = *(const unsigned int*)(g_edge + b * MM + k0);
    int p0 = (int)(pack2 & 0xFFFFu);
    int p1 = (int)(pack2 >> 16);
    float f0 = (k0     < K) ? 1.f : 0.f;
    float f1 = (k0 + 1 < K) ? 1.f : 0.f;

    const float4* pu = (const float4*)(g_proju + (size_t)b * NN * DD);
    const float4* pv = (const float4*)(g_projv + (size_t)b * NN * DD);

    float4 a0 = __ldg(&pu[((p0 >> 6) << 6) + lane]);
    float4 c0 = __ldg(&pv[((p0 & 63) << 6) + lane]);
    float4 a1 = __ldg(&pu[((p1 >> 6) << 6) + lane]);
    float4 c1 = __ldg(&pv[((p1 & 63) << 6) + lane]);

    float4 v0 = make_float4(f0 * (a0.x + c0.x), f0 * (a0.y + c0.y),
                            f0 * (a0.z + c0.z), f0 * (a0.w + c0.w));
    float4 v1 = make_float4(f1 * (a1.x + c1.x), f1 * (a1.y + c1.y),
                            f1 * (a1.z + c1.z), f1 * (a1.w + c1.w));

    float4* orow = (float4*)(out + ((size_t)b * SEQ + 1 + NN + k0) * DD);
    __stcs(&orow[lane], v0);
    __stcs(&orow[64 + lane], v1);
}

extern "C" void kernel_launch(void* const* d_in, const int* in_sizes, int n_in,
                              void* d_out, int out_size) {
    const int*   adj        = (const int*)d_in[0];
    const float* node_feats = (const float*)d_in[1];
    const float* eigvec     = (const float*)d_in[2];
    const float* W_lap      = (const float*)d_in[3];
    const float* W_edge     = (const float*)d_in[4];
    const float* b_edge     = (const float*)d_in[5];
    const float* type_embed = (const float*)d_in[6];
    const float* graph_tok  = (const float*)d_in[7];
    float* out = (float*)d_out;

    fused_proj_scan<<<320, 256>>>(node_feats, eigvec, W_lap, W_edge, b_edge,
                                  type_embed, graph_tok, adj, out);
    edge_kernel<<<dim3(252, 64), 256>>>(out);
}

// round 9
// speedup vs baseline: 1.3745x; 1.0285x over previous
#include <cuda_runtime.h>
#include <cstdint>
#include <math.h>

#define BB   64
#define NN   64
#define DD   256
#define LAPD 16
#define MM   2016          // N*(N-1)/2
#define SEQ  2081          // 1 + N + M

// Scratch (no allocation allowed in kernel_launch)
__device__ float g_proju[BB * NN * DD];   // 4 MB (C folded in)
__device__ float g_projv[BB * NN * DD];   // 4 MB
__device__ unsigned short g_edge[BB * MM];
__device__ int g_count[BB];

// Map linear upper-tri index m -> (i, j), i<j, row-major (triu_indices order)
__device__ __forceinline__ void m2ij(int m, int& i, int& j) {
    int ii = (int)((127.0 - sqrt(16129.0 - 8.0 * (double)m)) * 0.5);
    if (ii < 0) ii = 0;
    if (ii > 62) ii = 62;
    while (ii < 62 && (ii + 1) * (127 - (ii + 1)) / 2 <= m) ii++;
    while (ii > 0 && ii * (127 - ii) / 2 > m) ii--;
    i = ii;
    j = ii + 1 + (m - ii * (127 - ii) / 2);
}

// Fused: blocks [0,256) = proj; blocks [256,320) = scan + edge mask tail.
__global__ void fused_proj_scan(const float* __restrict__ node_feats,
                                const float* __restrict__ eigvec,
                                const float* __restrict__ W_lap,
                                const float* __restrict__ W_edge,
                                const float* __restrict__ b_edge,
                                const float* __restrict__ type_embed,
                                const float* __restrict__ graph_tok,
                                const int*  __restrict__ adj,
                                float* __restrict__ out) {
    __shared__ float sh[256];
    int tid = threadIdx.x;

    if (blockIdx.x < 256) {
        // ---------------- proj ----------------
        int b  = blockIdx.x >> 2;
        int g  = blockIdx.x & 3;
        int n0 = g * 16;
        int d  = tid;

        float wl[LAPD], wu[LAPD], wv[LAPD];
#pragma unroll
        for (int l = 0; l < LAPD; l++) {
            wl[l] = __ldg(&W_lap[l * DD + d]);
            wu[l] = __ldg(&W_edge[(1 + l) * DD + d]);
            wv[l] = __ldg(&W_edge[(1 + LAPD + l) * DD + d]);
        }
        float Cd = __ldg(&W_edge[d]) + __ldg(&b_edge[d]) + __ldg(&type_embed[DD + d]);

        sh[tid] = eigvec[(size_t)(b * NN + n0) * LAPD + tid];
        __syncthreads();

#pragma unroll 4
        for (int n = 0; n < 16; n++) {
            int node = b * NN + n0 + n;
            float nt = node_feats[(size_t)node * DD + d];
            float pu = 0.f, pv = 0.f;
#pragma unroll
            for (int l = 0; l < LAPD; l++) {
                float ev = sh[n * LAPD + l];
                nt += ev * wl[l];
                pu += ev * wu[l];
                pv += ev * wv[l];
            }
            __stcs(&out[((size_t)b * SEQ + 1 + n0 + n) * DD + d], nt);
            g_proju[(size_t)node * DD + d] = pu + Cd;
            g_projv[(size_t)node * DD + d] = pv;
        }

        if (g == 0) {
            __stcs(&out[(size_t)b * SEQ * DD + d], graph_tok[d]);
            float* maskf = out + (size_t)BB * SEQ * DD;
            if (d < 1 + NN) maskf[(size_t)b * SEQ + d] = 0.f;
        }
    } else {
        // ---------------- scan + mask tail ----------------
        int b = blockIdx.x - 256;
        int* s = (int*)sh;
        const int* adjb = adj + (size_t)b * NN * NN;

        int m0 = tid * 8;
        int i, j;
        int v[8], ij[8];
        int local = 0;
        if (m0 < MM) {
            m2ij(m0, i, j);
#pragma unroll
            for (int q = 0; q < 8; q++) {
                int m = m0 + q;
                int val = 0, pack = 0;
                if (m < MM) {
                    pack = (i << 6) | j;
                    val = adjb[i * NN + j] > 0;
                    j++;
                    if (j == NN) { i++; j = i + 1; }
                }
                v[q] = val; ij[q] = pack;
                local += val;
            }
        } else {
#pragma unroll
            for (int q = 0; q < 8; q++) { v[q] = 0; ij[q] = 0; }
        }

        s[tid] = local;
        __syncthreads();
#pragma unroll
        for (int off = 1; off < 256; off <<= 1) {
            int add = (tid >= off) ? s[tid - off] : 0;
            __syncthreads();
            s[tid] += add;
            __syncthreads();
        }
        int pos = s[tid] - local;
#pragma unroll
        for (int q = 0; q < 8; q++) {
            if (v[q]) g_edge[b * MM + pos++] = (unsigned short)ij[q];
        }
        int total = s[255];
        if (tid == 255) g_count[b] = total;

        float* maskf = out + (size_t)BB * SEQ * DD + (size_t)b * SEQ + 1 + NN;
        for (int k = tid; k < MM; k += 256)
            maskf[k] = (k < total) ? 0.f : 1.f;
    }
}

// Edge kernel: grid (252, 64), 256 threads. 8 rows/block; each 64-lane group
// handles 2 ADJACENT rows (one u32 load covers both u16 edge indices).
// Indices CLAMPED to 0 for padding rows so all padding gathers hit one hot
// L1 line. No smem, no division, streaming float4 stores.
__global__ void __launch_bounds__(256, 8) edge_kernel(float* __restrict__ out) {
    int b    = blockIdx.y;
    int tid  = threadIdx.x;
    int rg   = tid >> 6;                   // 0..3
    int lane = tid & 63;
    int k0   = (blockIdx.x << 3) + (rg << 1);   // adjacent pair k0, k0+1
    int K    = g_count[b];

    // one 32-bit load -> both u16 indices (aligned: k0 even)
    unsigned int pack2 = *(const unsigned int*)(g_edge + b * MM + k0);
    bool val0 = (k0     < K);
    bool val1 = (k0 + 1 < K);
    int p0 = val0 ? (int)(pack2 & 0xFFFFu) : 0;
    int p1 = val1 ? (int)(pack2 >> 16)     : 0;
    float f0 = val0 ? 1.f : 0.f;
    float f1 = val1 ? 1.f : 0.f;

    const float4* pu = (const float4*)(g_proju + (size_t)b * NN * DD);
    const float4* pv = (const float4*)(g_projv + (size_t)b * NN * DD);

    float4 a0 = __ldg(&pu[((p0 >> 6) << 6) + lane]);
    float4 c0 = __ldg(&pv[((p0 & 63) << 6) + lane]);
    float4 a1 = __ldg(&pu[((p1 >> 6) << 6) + lane]);
    float4 c1 = __ldg(&pv[((p1 & 63) << 6) + lane]);

    float4 v0 = make_float4(f0 * (a0.x + c0.x), f0 * (a0.y + c0.y),
                            f0 * (a0.z + c0.z), f0 * (a0.w + c0.w));
    float4 v1 = make_float4(f1 * (a1.x + c1.x), f1 * (a1.y + c1.y),
                            f1 * (a1.z + c1.z), f1 * (a1.w + c1.w));

    float4* orow = (float4*)(out + ((size_t)b * SEQ + 1 + NN + k0) * DD);
    __stcs(&orow[lane], v0);
    __stcs(&orow[64 + lane], v1);
}

extern "C" void kernel_launch(void* const* d_in, const int* in_sizes, int n_in,
                              void* d_out, int out_size) {
    const int*   adj        = (const int*)d_in[0];
    const float* node_feats = (const float*)d_in[1];
    const float* eigvec     = (const float*)d_in[2];
    const float* W_lap      = (const float*)d_in[3];
    const float* W_edge     = (const float*)d_in[4];
    const float* b_edge     = (const float*)d_in[5];
    const float* type_embed = (const float*)d_in[6];
    const float* graph_tok  = (const float*)d_in[7];
    float* out = (float*)d_out;

    fused_proj_scan<<<320, 256>>>(node_feats, eigvec, W_lap, W_edge, b_edge,
                                  type_embed, graph_tok, adj, out);
    edge_kernel<<<dim3(252, 64), 256>>>(out);
}

// round 10
// speedup vs baseline: 1.4303x; 1.0406x over previous
#include <cuda_runtime.h>
#include <cstdint>
#include <math.h>

#define BB   64
#define NN   64
#define DD   256
#define LAPD 16
#define MM   2016          // N*(N-1)/2
#define SEQ  2081          // 1 + N + M

// Scratch (no allocation allowed in kernel_launch)
__device__ float g_proju[BB * NN * DD];   // 4 MB (C folded in)
__device__ float g_projv[BB * NN * DD];   // 4 MB
__device__ unsigned short g_edge[BB * MM];
__device__ int g_count[BB];

// Map linear upper-tri index m -> (i, j), i<j, row-major (triu_indices order)
__device__ __forceinline__ void m2ij(int m, int& i, int& j) {
    int ii = (int)((127.0 - sqrt(16129.0 - 8.0 * (double)m)) * 0.5);
    if (ii < 0) ii = 0;
    if (ii > 62) ii = 62;
    while (ii < 62 && (ii + 1) * (127 - (ii + 1)) / 2 <= m) ii++;
    while (ii > 0 && ii * (127 - ii) / 2 > m) ii--;
    i = ii;
    j = ii + 1 + (m - ii * (127 - ii) / 2);
}

// Fused: blocks [0,256) = proj; blocks [256,320) = scan + edge mask tail.
__global__ void fused_proj_scan(const float* __restrict__ node_feats,
                                const float* __restrict__ eigvec,
                                const float* __restrict__ W_lap,
                                const float* __restrict__ W_edge,
                                const float* __restrict__ b_edge,
                                const float* __restrict__ type_embed,
                                const float* __restrict__ graph_tok,
                                const int*  __restrict__ adj,
                                float* __restrict__ out) {
    __shared__ float sh[256];
    int tid = threadIdx.x;

    if (blockIdx.x < 256) {
        // ---------------- proj ----------------
        int b  = blockIdx.x >> 2;
        int g  = blockIdx.x & 3;
        int n0 = g * 16;
        int d  = tid;

        float wl[LAPD], wu[LAPD], wv[LAPD];
#pragma unroll
        for (int l = 0; l < LAPD; l++) {
            wl[l] = __ldg(&W_lap[l * DD + d]);
            wu[l] = __ldg(&W_edge[(1 + l) * DD + d]);
            wv[l] = __ldg(&W_edge[(1 + LAPD + l) * DD + d]);
        }
        float Cd = __ldg(&W_edge[d]) + __ldg(&b_edge[d]) + __ldg(&type_embed[DD + d]);

        sh[tid] = eigvec[(size_t)(b * NN + n0) * LAPD + tid];
        __syncthreads();

#pragma unroll 4
        for (int n = 0; n < 16; n++) {
            int node = b * NN + n0 + n;
            float nt = node_feats[(size_t)node * DD + d];
            float pu = 0.f, pv = 0.f;
#pragma unroll
            for (int l = 0; l < LAPD; l++) {
                float ev = sh[n * LAPD + l];
                nt += ev * wl[l];
                pu += ev * wu[l];
                pv += ev * wv[l];
            }
            __stcs(&out[((size_t)b * SEQ + 1 + n0 + n) * DD + d], nt);
            g_proju[(size_t)node * DD + d] = pu + Cd;
            g_projv[(size_t)node * DD + d] = pv;
        }

        if (g == 0) {
            __stcs(&out[(size_t)b * SEQ * DD + d], graph_tok[d]);
            float* maskf = out + (size_t)BB * SEQ * DD;
            if (d < 1 + NN) maskf[(size_t)b * SEQ + d] = 0.f;
        }
    } else {
        // ---------------- scan + mask tail ----------------
        int b = blockIdx.x - 256;
        int* s = (int*)sh;
        const int* adjb = adj + (size_t)b * NN * NN;

        int m0 = tid * 8;
        int i, j;
        int v[8], ij[8];
        int local = 0;
        if (m0 < MM) {
            m2ij(m0, i, j);
#pragma unroll
            for (int q = 0; q < 8; q++) {
                int m = m0 + q;
                int val = 0, pack = 0;
                if (m < MM) {
                    pack = (i << 6) | j;
                    val = adjb[i * NN + j] > 0;
                    j++;
                    if (j == NN) { i++; j = i + 1; }
                }
                v[q] = val; ij[q] = pack;
                local += val;
            }
        } else {
#pragma unroll
            for (int q = 0; q < 8; q++) { v[q] = 0; ij[q] = 0; }
        }

        s[tid] = local;
        __syncthreads();
#pragma unroll
        for (int off = 1; off < 256; off <<= 1) {
            int add = (tid >= off) ? s[tid - off] : 0;
            __syncthreads();
            s[tid] += add;
            __syncthreads();
        }
        int pos = s[tid] - local;
#pragma unroll
        for (int q = 0; q < 8; q++) {
            if (v[q]) g_edge[b * MM + pos++] = (unsigned short)ij[q];
        }
        int total = s[255];
        if (tid == 255) g_count[b] = total;

        float* maskf = out + (size_t)BB * SEQ * DD + (size_t)b * SEQ + 1 + NN;
        for (int k = tid; k < MM; k += 256)
            maskf[k] = (k < total) ? 0.f : 1.f;
    }
}

// Edge kernel: grid (252, 64), 256 threads. 8 rows/block; each 64-lane group
// handles 2 ADJACENT rows. Gathers issued ONLY for valid rows (padding tail
// takes a store-only zero path; branch is uniform per group except at the
// K boundary). One u32 index load covers both u16 indices.
__global__ void __launch_bounds__(256, 8) edge_kernel(float* __restrict__ out) {
    int b    = blockIdx.y;
    int tid  = threadIdx.x;
    int rg   = tid >> 6;                   // 0..3
    int lane = tid & 63;
    int k0   = (blockIdx.x << 3) + (rg << 1);   // adjacent pair k0, k0+1
    int K    = g_count[b];

    float4 v0 = make_float4(0.f, 0.f, 0.f, 0.f);
    float4 v1 = v0;

    if (k0 < K) {
        unsigned int pack2 = *(const unsigned int*)(g_edge + b * MM + k0);
        int p0 = (int)(pack2 & 0xFFFFu);
        int p1 = (int)(pack2 >> 16);

        const float4* pu = (const float4*)(g_proju + (size_t)b * NN * DD);
        const float4* pv = (const float4*)(g_projv + (size_t)b * NN * DD);

        float4 a0 = __ldg(&pu[((p0 >> 6) << 6) + lane]);
        float4 c0 = __ldg(&pv[((p0 & 63) << 6) + lane]);
        v0 = make_float4(a0.x + c0.x, a0.y + c0.y, a0.z + c0.z, a0.w + c0.w);

        if (k0 + 1 < K) {
            float4 a1 = __ldg(&pu[((p1 >> 6) << 6) + lane]);
            float4 c1 = __ldg(&pv[((p1 & 63) << 6) + lane]);
            v1 = make_float4(a1.x + c1.x, a1.y + c1.y, a1.z + c1.z, a1.w + c1.w);
        }
    }

    float4* orow = (float4*)(out + ((size_t)b * SEQ + 1 + NN + k0) * DD);
    __stcs(&orow[lane], v0);
    __stcs(&orow[64 + lane], v1);
}

extern "C" void kernel_launch(void* const* d_in, const int* in_sizes, int n_in,
                              void* d_out, int out_size) {
    const int*   adj        = (const int*)d_in[0];
    const float* node_feats = (const float*)d_in[1];
    const float* eigvec     = (const float*)d_in[2];
    const float* W_lap      = (const float*)d_in[3];
    const float* W_edge     = (const float*)d_in[4];
    const float* b_edge     = (const float*)d_in[5];
    const float* type_embed = (const float*)d_in[6];
    const float* graph_tok  = (const float*)d_in[7];
    float* out = (float*)d_out;

    fused_proj_scan<<<320, 256>>>(node_feats, eigvec, W_lap, W_edge, b_edge,
                                  type_embed, graph_tok, adj, out);
    edge_kernel<<<dim3(252, 64), 256>>>(out);
}